// round 1
// baseline (speedup 1.0000x reference)
#include <cuda_runtime.h>

// Problem constants
#define IN_F   2048
#define OUT_F  4096
#define BATCHN 131072

// Scratch (static device globals — allocation-free per harness rules).
// All of it is fully overwritten every kernel_launch call, so graph replays
// are deterministic.
__device__ float g_partial[32 * IN_F];   // per-row-slice partial sums of weight
__device__ float g_wsum[IN_F];           // weight.sum(axis=0)
__device__ float g_bsum;                 // bias.sum()

// ---------------------------------------------------------------------------
// Kernel 1: partial column-sums of weight.
// grid = (IN_F/256, 32), block = 256.
// Block (bx, by) sums weight rows [by*128, by*128+128) for columns
// [bx*256, bx*256+256). Fully coalesced: consecutive threads read consecutive
// columns within a row.
// ---------------------------------------------------------------------------
__global__ void reduce_weight_kernel(const float* __restrict__ weight) {
    const int c = blockIdx.x * 256 + threadIdx.x;      // column
    const int r0 = blockIdx.y * 128;                   // first row of slice
    float s = 0.0f;
    const float* wp = weight + (size_t)r0 * IN_F + c;
    #pragma unroll 8
    for (int r = 0; r < 128; ++r) {
        s += wp[(size_t)r * IN_F];
    }
    g_partial[blockIdx.y * IN_F + c] = s;
}

// ---------------------------------------------------------------------------
// Kernel 2: fold 32 partials -> w_sum; block 8 also reduces bias -> b_sum.
// grid = 9, block = 256. Fixed-order summation => deterministic.
// ---------------------------------------------------------------------------
__global__ void finalize_kernel(const float* __restrict__ bias) {
    if (blockIdx.x < 8) {
        const int c = blockIdx.x * 256 + threadIdx.x;
        float s = 0.0f;
        #pragma unroll
        for (int p = 0; p < 32; ++p) {
            s += g_partial[p * IN_F + c];
        }
        g_wsum[c] = s;
    } else {
        // bias reduction: 4096 elements, 256 threads -> 16 each, then
        // shared-memory tree reduce (deterministic order).
        __shared__ float red[256];
        float s = 0.0f;
        #pragma unroll
        for (int i = 0; i < OUT_F / 256; ++i) {
            s += bias[i * 256 + threadIdx.x];
        }
        red[threadIdx.x] = s;
        __syncthreads();
        #pragma unroll
        for (int stride = 128; stride > 0; stride >>= 1) {
            if (threadIdx.x < stride) red[threadIdx.x] += red[threadIdx.x + stride];
            __syncthreads();
        }
        if (threadIdx.x == 0) g_bsum = red[0];
    }
}

// ---------------------------------------------------------------------------
// Kernel 3: out[row] = dot(x[row,:], w_sum) + b_sum.
// Warp-per-row. block = 256 (8 warps), grid = BATCH/8 = 16384.
// w_sum staged in shared once per block (8 KB). Each lane issues 16
// independent float4 loads (512 B contiguous per warp per iteration,
// MLP=16 to hide DRAM latency), then a warp shuffle reduction.
// ---------------------------------------------------------------------------
__global__ __launch_bounds__(256) void gemv_kernel(const float* __restrict__ x,
                                                   float* __restrict__ out) {
    __shared__ float4 sw[IN_F / 4];   // 512 float4 = 8 KB
    __shared__ float sb;

    const int tid = threadIdx.x;
    // Stage w_sum into shared.
    #pragma unroll
    for (int i = 0; i < (IN_F / 4) / 256; ++i) {
        sw[i * 256 + tid] = reinterpret_cast<const float4*>(g_wsum)[i * 256 + tid];
    }
    if (tid == 0) sb = g_bsum;
    __syncthreads();

    const int warp = tid >> 5;
    const int lane = tid & 31;
    const int row  = blockIdx.x * 8 + warp;

    const float4* xr = reinterpret_cast<const float4*>(x + (size_t)row * IN_F);

    float acc = 0.0f;
    #pragma unroll
    for (int i = 0; i < 16; ++i) {          // 16 * 32 lanes * 4 floats = 2048
        const float4 xv = xr[i * 32 + lane];
        const float4 wv = sw[i * 32 + lane];
        acc += xv.x * wv.x + xv.y * wv.y + xv.z * wv.z + xv.w * wv.w;
    }

    // Warp reduction
    #pragma unroll
    for (int off = 16; off > 0; off >>= 1) {
        acc += __shfl_xor_sync(0xFFFFFFFFu, acc, off);
    }
    if (lane == 0) {
        out[row] = acc + sb;
    }
}

// ---------------------------------------------------------------------------
extern "C" void kernel_launch(void* const* d_in, const int* in_sizes, int n_in,
                              void* d_out, int out_size) {
    const float* x      = (const float*)d_in[0];  // (131072, 2048)
    const float* weight = (const float*)d_in[1];  // (4096, 2048)
    const float* bias   = (const float*)d_in[2];  // (4096,)
    float* out = (float*)d_out;                   // (131072, 1)

    (void)in_sizes; (void)n_in; (void)out_size;

    dim3 g1(IN_F / 256, 32);
    reduce_weight_kernel<<<g1, 256>>>(weight);
    finalize_kernel<<<9, 256>>>(bias);
    gemv_kernel<<<BATCHN / 8, 256>>>(x, out);
}